// round 1
// baseline (speedup 1.0000x reference)
#include <cuda_runtime.h>
#include <cuda_bf16.h>
#include <cstdint>

#define T_TOKENS 32768
#define D_DIM    512
#define F_DIM    2048
#define N_EXP    64

// ---------------- scratch (device globals: allocation-free rule) ----------------
__device__ int   g_counts[N_EXP];
__device__ int   g_offsets[N_EXP + 1];
__device__ int   g_fill[N_EXP];
__device__ int   g_tok[T_TOKENS];
__device__ float g_H[(size_t)T_TOKENS * F_DIM];   // 256 MB intermediate

// ---------------- helpers ----------------
__device__ __forceinline__ float tf32_round(float x) {
    uint32_t u;
    asm("cvt.rna.tf32.f32 %0, %1;" : "=r"(u) : "f"(x));
    return __uint_as_float(u);
}

__device__ __forceinline__ void mma_tf32(float* c, const uint32_t* a, const uint32_t* b) {
    asm volatile(
        "mma.sync.aligned.m16n8k8.row.col.f32.tf32.tf32.f32 "
        "{%0,%1,%2,%3}, {%4,%5,%6,%7}, {%8,%9}, {%0,%1,%2,%3};"
        : "+f"(c[0]), "+f"(c[1]), "+f"(c[2]), "+f"(c[3])
        : "r"(a[0]), "r"(a[1]), "r"(a[2]), "r"(a[3]), "r"(b[0]), "r"(b[1]));
}

__device__ __forceinline__ float gelu_exact(float x) {
    return 0.5f * x * (1.0f + erff(x * 0.70710678118654752f));
}

// ---------------- bookkeeping ----------------
__global__ void init_kernel() {
    int i = threadIdx.x;
    if (i < N_EXP) { g_counts[i] = 0; g_fill[i] = 0; }
}

__global__ void count_kernel(const int* __restrict__ disp) {
    int t = blockIdx.x * blockDim.x + threadIdx.x;
    if (t < T_TOKENS) atomicAdd(&g_counts[disp[t]], 1);
}

__global__ void scan_kernel() {
    if (threadIdx.x == 0) {
        int s = 0;
        for (int i = 0; i < N_EXP; i++) { g_offsets[i] = s; s += g_counts[i]; }
        g_offsets[N_EXP] = s;
    }
}

__global__ void fill_kernel(const int* __restrict__ disp) {
    int t = blockIdx.x * blockDim.x + threadIdx.x;
    if (t < T_TOKENS) {
        int e = disp[t];
        int p = atomicAdd(&g_fill[e], 1);
        g_tok[g_offsets[e] + p] = t;
    }
}

// ---------------- GEMM1: H = gelu(X_gathered @ W1 + b1) ----------------
// CTA tile 128(M) x 128(N), BK=32. Grid: (F/128=16, capacity/128=8, 64 experts)
__global__ __launch_bounds__(256) void gemm1_kernel(
    const float* __restrict__ X, const float* __restrict__ W1, const float* __restrict__ B1)
{
    __shared__ float As[128][36];
    __shared__ float Bs[32][132];
    __shared__ int   stoks[128];

    const int e    = blockIdx.z;
    const int base = g_offsets[e];
    const int ne   = g_offsets[e + 1] - base;
    const int tm   = blockIdx.y * 128;
    if (tm >= ne) return;
    const int n0   = blockIdx.x * 128;

    const int tid  = threadIdx.x;
    const int warp = tid >> 5, lane = tid & 31;
    const int g    = lane >> 2, t = lane & 3;
    const int wm   = (warp & 3) * 32;   // warp M offset
    const int wn   = (warp >> 2) * 64;  // warp N offset

    if (tid < 128) stoks[tid] = (tm + tid < ne) ? g_tok[base + tm + tid] : -1;

    float acc[2][8][4];
#pragma unroll
    for (int mf = 0; mf < 2; mf++)
#pragma unroll
        for (int nf = 0; nf < 8; nf++)
#pragma unroll
            for (int c = 0; c < 4; c++) acc[mf][nf][c] = 0.f;

    const int KIT = D_DIM / 32;  // 16
    for (int kt = 0; kt < KIT; kt++) {
        const int k0 = kt * 32;
        __syncthreads();
        // A: 128 rows x 32 cols (gathered, tf32-rounded)
#pragma unroll
        for (int i = 0; i < 4; i++) {
            int idx = tid + i * 256;
            int r = idx >> 3, c4 = (idx & 7) * 4;
            int tok = stoks[r];
            float4 v = make_float4(0.f, 0.f, 0.f, 0.f);
            if (tok >= 0) v = *reinterpret_cast<const float4*>(&X[(size_t)tok * D_DIM + k0 + c4]);
            As[r][c4 + 0] = tf32_round(v.x);
            As[r][c4 + 1] = tf32_round(v.y);
            As[r][c4 + 2] = tf32_round(v.z);
            As[r][c4 + 3] = tf32_round(v.w);
        }
        // B: 32 rows(k) x 128 cols(n)
#pragma unroll
        for (int i = 0; i < 4; i++) {
            int idx = tid + i * 256;
            int kr = idx >> 5, c4 = (idx & 31) * 4;
            float4 v = *reinterpret_cast<const float4*>(
                &W1[((size_t)e * D_DIM + (k0 + kr)) * F_DIM + n0 + c4]);
            Bs[kr][c4 + 0] = tf32_round(v.x);
            Bs[kr][c4 + 1] = tf32_round(v.y);
            Bs[kr][c4 + 2] = tf32_round(v.z);
            Bs[kr][c4 + 3] = tf32_round(v.w);
        }
        __syncthreads();

#pragma unroll
        for (int ks = 0; ks < 4; ks++) {
            const int kk = ks * 8;
            uint32_t a[2][4];
#pragma unroll
            for (int mf = 0; mf < 2; mf++) {
                int row = wm + mf * 16;
                a[mf][0] = __float_as_uint(As[row + g][kk + t]);
                a[mf][1] = __float_as_uint(As[row + g + 8][kk + t]);
                a[mf][2] = __float_as_uint(As[row + g][kk + t + 4]);
                a[mf][3] = __float_as_uint(As[row + g + 8][kk + t + 4]);
            }
            uint32_t b[8][2];
#pragma unroll
            for (int nf = 0; nf < 8; nf++) {
                int col = wn + nf * 8 + g;
                b[nf][0] = __float_as_uint(Bs[kk + t][col]);
                b[nf][1] = __float_as_uint(Bs[kk + t + 4][col]);
            }
#pragma unroll
            for (int mf = 0; mf < 2; mf++)
#pragma unroll
                for (int nf = 0; nf < 8; nf++)
                    mma_tf32(acc[mf][nf], a[mf], b[nf]);
        }
    }

    // epilogue: bias + exact gelu -> g_H (compact rows)
#pragma unroll
    for (int mf = 0; mf < 2; mf++) {
#pragma unroll
        for (int nf = 0; nf < 8; nf++) {
            int row0 = wm + mf * 16 + g;
            int col  = n0 + wn + nf * 8 + t * 2;
            float b0 = B1[e * F_DIM + col];
            float b1v = B1[e * F_DIM + col + 1];
            int lr = tm + row0;
            if (lr < ne) {
                float2 h;
                h.x = gelu_exact(acc[mf][nf][0] + b0);
                h.y = gelu_exact(acc[mf][nf][1] + b1v);
                *reinterpret_cast<float2*>(&g_H[(size_t)(base + lr) * F_DIM + col]) = h;
            }
            int lr2 = lr + 8;
            if (lr2 < ne) {
                float2 h;
                h.x = gelu_exact(acc[mf][nf][2] + b0);
                h.y = gelu_exact(acc[mf][nf][3] + b1v);
                *reinterpret_cast<float2*>(&g_H[(size_t)(base + lr2) * F_DIM + col]) = h;
            }
        }
    }
}

// ---------------- GEMM2: out_scattered = H @ W2 + b2 ----------------
// Grid: (D/128=4, capacity/128=8, 64 experts)
__global__ __launch_bounds__(256) void gemm2_kernel(
    const float* __restrict__ W2, const float* __restrict__ B2, float* __restrict__ out)
{
    __shared__ float As[128][36];
    __shared__ float Bs[32][132];
    __shared__ int   stoks[128];

    const int e    = blockIdx.z;
    const int base = g_offsets[e];
    const int ne   = g_offsets[e + 1] - base;
    const int tm   = blockIdx.y * 128;
    if (tm >= ne) return;
    const int n0   = blockIdx.x * 128;

    const int tid  = threadIdx.x;
    const int warp = tid >> 5, lane = tid & 31;
    const int g    = lane >> 2, t = lane & 3;
    const int wm   = (warp & 3) * 32;
    const int wn   = (warp >> 2) * 64;

    if (tid < 128) stoks[tid] = (tm + tid < ne) ? g_tok[base + tm + tid] : -1;

    float acc[2][8][4];
#pragma unroll
    for (int mf = 0; mf < 2; mf++)
#pragma unroll
        for (int nf = 0; nf < 8; nf++)
#pragma unroll
            for (int c = 0; c < 4; c++) acc[mf][nf][c] = 0.f;

    const int KIT = F_DIM / 32;  // 64
    for (int kt = 0; kt < KIT; kt++) {
        const int k0 = kt * 32;
        __syncthreads();
#pragma unroll
        for (int i = 0; i < 4; i++) {
            int idx = tid + i * 256;
            int r = idx >> 3, c4 = (idx & 7) * 4;
            float4 v = make_float4(0.f, 0.f, 0.f, 0.f);
            if (tm + r < ne)
                v = *reinterpret_cast<const float4*>(&g_H[(size_t)(base + tm + r) * F_DIM + k0 + c4]);
            As[r][c4 + 0] = tf32_round(v.x);
            As[r][c4 + 1] = tf32_round(v.y);
            As[r][c4 + 2] = tf32_round(v.z);
            As[r][c4 + 3] = tf32_round(v.w);
        }
#pragma unroll
        for (int i = 0; i < 4; i++) {
            int idx = tid + i * 256;
            int kr = idx >> 5, c4 = (idx & 31) * 4;
            float4 v = *reinterpret_cast<const float4*>(
                &W2[((size_t)e * F_DIM + (k0 + kr)) * D_DIM + n0 + c4]);
            Bs[kr][c4 + 0] = tf32_round(v.x);
            Bs[kr][c4 + 1] = tf32_round(v.y);
            Bs[kr][c4 + 2] = tf32_round(v.z);
            Bs[kr][c4 + 3] = tf32_round(v.w);
        }
        __syncthreads();

#pragma unroll
        for (int ks = 0; ks < 4; ks++) {
            const int kk = ks * 8;
            uint32_t a[2][4];
#pragma unroll
            for (int mf = 0; mf < 2; mf++) {
                int row = wm + mf * 16;
                a[mf][0] = __float_as_uint(As[row + g][kk + t]);
                a[mf][1] = __float_as_uint(As[row + g + 8][kk + t]);
                a[mf][2] = __float_as_uint(As[row + g][kk + t + 4]);
                a[mf][3] = __float_as_uint(As[row + g + 8][kk + t + 4]);
            }
            uint32_t b[8][2];
#pragma unroll
            for (int nf = 0; nf < 8; nf++) {
                int col = wn + nf * 8 + g;
                b[nf][0] = __float_as_uint(Bs[kk + t][col]);
                b[nf][1] = __float_as_uint(Bs[kk + t + 4][col]);
            }
#pragma unroll
            for (int mf = 0; mf < 2; mf++)
#pragma unroll
                for (int nf = 0; nf < 8; nf++)
                    mma_tf32(acc[mf][nf], a[mf], b[nf]);
        }
    }

    // epilogue: bias + scatter to out[token]
#pragma unroll
    for (int mf = 0; mf < 2; mf++) {
#pragma unroll
        for (int nf = 0; nf < 8; nf++) {
            int row0 = wm + mf * 16 + g;
            int col  = n0 + wn + nf * 8 + t * 2;
            float b0 = B2[e * D_DIM + col];
            float b1v = B2[e * D_DIM + col + 1];
            int lr = tm + row0;
            if (lr < ne) {
                int tok = stoks[row0];
                float2 o;
                o.x = acc[mf][nf][0] + b0;
                o.y = acc[mf][nf][1] + b1v;
                *reinterpret_cast<float2*>(&out[(size_t)tok * D_DIM + col]) = o;
            }
            int lr2 = lr + 8;
            if (lr2 < ne) {
                int tok = stoks[row0 + 8];
                float2 o;
                o.x = acc[mf][nf][2] + b0;
                o.y = acc[mf][nf][3] + b1v;
                *reinterpret_cast<float2*>(&out[(size_t)tok * D_DIM + col]) = o;
            }
        }
    }
}

// ---------------- launch ----------------
extern "C" void kernel_launch(void* const* d_in, const int* in_sizes, int n_in,
                              void* d_out, int out_size)
{
    const float* X    = (const float*)d_in[0];
    const int*   disp = (const int*)d_in[1];
    const float* W1   = (const float*)d_in[2];
    const float* B1   = (const float*)d_in[3];
    const float* W2   = (const float*)d_in[4];
    const float* B2   = (const float*)d_in[5];
    float*       out  = (float*)d_out;

    init_kernel<<<1, 64>>>();
    count_kernel<<<T_TOKENS / 256, 256>>>(disp);
    scan_kernel<<<1, 1>>>();
    fill_kernel<<<T_TOKENS / 256, 256>>>(disp);
    gemm1_kernel<<<dim3(F_DIM / 128, 8, N_EXP), 256>>>(X, W1, B1);
    gemm2_kernel<<<dim3(D_DIM / 128, 8, N_EXP), 256>>>(W2, B2, out);
}

// round 4
// speedup vs baseline: 1.2720x; 1.2720x over previous
#include <cuda_runtime.h>
#include <cuda_bf16.h>
#include <cstdint>

#define T_TOKENS 32768
#define D_DIM    512
#define F_DIM    2048
#define N_EXP    64

#define BM 128
#define BN 128
#define BK 32
#define NTHREADS 128

// ---------------- scratch (device globals: allocation-free rule) ----------------
__device__ int   g_counts[N_EXP];
__device__ int   g_offsets[N_EXP + 1];
__device__ int   g_fill[N_EXP];
__device__ int   g_tok[T_TOKENS];
__device__ float g_H[(size_t)T_TOKENS * F_DIM];   // 256 MB intermediate

// smem layout (dynamic): A[2][128*36] then B[2][32*132]
#define A_STRIDE 36
#define B_STRIDE 132
#define A_STAGE  (BM * A_STRIDE)          // floats
#define B_STAGE  (BK * B_STRIDE)          // floats
#define SMEM_FLOATS (2 * A_STAGE + 2 * B_STAGE)
#define SMEM_BYTES  (SMEM_FLOATS * 4)

// ---------------- helpers ----------------
__device__ __forceinline__ uint32_t f2tf(float x) {
    uint32_t u;
    asm("cvt.rna.tf32.f32 %0, %1;" : "=r"(u) : "f"(x));
    return u;
}

__device__ __forceinline__ void mma_tf32(float* c, const uint32_t* a, const uint32_t* b) {
    asm volatile(
        "mma.sync.aligned.m16n8k8.row.col.f32.tf32.tf32.f32 "
        "{%0,%1,%2,%3}, {%4,%5,%6,%7}, {%8,%9}, {%0,%1,%2,%3};"
        : "+f"(c[0]), "+f"(c[1]), "+f"(c[2]), "+f"(c[3])
        : "r"(a[0]), "r"(a[1]), "r"(a[2]), "r"(a[3]), "r"(b[0]), "r"(b[1]));
}

__device__ __forceinline__ void cp16(uint32_t dst, const void* src, int szbytes) {
    asm volatile("cp.async.cg.shared.global [%0], [%1], 16, %2;"
                 :: "r"(dst), "l"(src), "r"(szbytes));
}

__device__ __forceinline__ float gelu_exact(float x) {
    return 0.5f * x * (1.0f + erff(x * 0.70710678118654752f));
}

// ---------------- bookkeeping ----------------
__global__ void init_kernel() {
    int i = threadIdx.x;
    if (i < N_EXP) { g_counts[i] = 0; g_fill[i] = 0; }
}

__global__ void count_kernel(const int* __restrict__ disp) {
    int t = blockIdx.x * blockDim.x + threadIdx.x;
    if (t < T_TOKENS) atomicAdd(&g_counts[disp[t]], 1);
}

__global__ void scan_kernel() {
    if (threadIdx.x == 0) {
        int s = 0;
        for (int i = 0; i < N_EXP; i++) { g_offsets[i] = s; s += g_counts[i]; }
        g_offsets[N_EXP] = s;
    }
}

__global__ void fill_kernel(const int* __restrict__ disp) {
    int t = blockIdx.x * blockDim.x + threadIdx.x;
    if (t < T_TOKENS) {
        int e = disp[t];
        int p = atomicAdd(&g_fill[e], 1);
        g_tok[g_offsets[e] + p] = t;
    }
}

// ================= GEMM core macro pieces =================
// 4 warps in 2x2; warp tile 64x64; per-warp: mf 0..3 (16-row), nf 0..7 (8-col)

// compute one BK=32 tile from smem stage (sA/sB point at stage base)
__device__ __forceinline__ void compute_tile(const float* __restrict__ sA,
                                             const float* __restrict__ sB,
                                             int wm, int wn, int g, int t,
                                             float acc[4][8][4])
{
#pragma unroll
    for (int ks = 0; ks < 4; ks++) {
        const int kk = ks * 8;
        uint32_t a[4][4];
#pragma unroll
        for (int mf = 0; mf < 4; mf++) {
            int row = wm + mf * 16 + g;
            a[mf][0] = f2tf(sA[row * A_STRIDE + kk + t]);
            a[mf][1] = f2tf(sA[(row + 8) * A_STRIDE + kk + t]);
            a[mf][2] = f2tf(sA[row * A_STRIDE + kk + t + 4]);
            a[mf][3] = f2tf(sA[(row + 8) * A_STRIDE + kk + t + 4]);
        }
        uint32_t b[8][2];
#pragma unroll
        for (int nf = 0; nf < 8; nf++) {
            int col = wn + nf * 8 + g;
            b[nf][0] = f2tf(sB[(kk + t) * B_STRIDE + col]);
            b[nf][1] = f2tf(sB[(kk + t + 4) * B_STRIDE + col]);
        }
#pragma unroll
        for (int mf = 0; mf < 4; mf++)
#pragma unroll
            for (int nf = 0; nf < 8; nf++)
                mma_tf32(acc[mf][nf], a[mf], b[nf]);
    }
}

// ---------------- GEMM1: H = gelu(X_gathered @ W1 + b1) ----------------
// Grid: (F/128=16, 8, 64), 128 threads
__global__ __launch_bounds__(NTHREADS) void gemm1_kernel(
    const float* __restrict__ X, const float* __restrict__ W1, const float* __restrict__ B1)
{
    extern __shared__ float smem[];
    __shared__ int stoks[BM];

    const int e    = blockIdx.z;
    const int base = g_offsets[e];
    const int ne   = g_offsets[e + 1] - base;
    const int tm   = blockIdx.y * BM;
    if (tm >= ne) return;
    const int n0   = blockIdx.x * BN;

    const int tid  = threadIdx.x;
    const int warp = tid >> 5, lane = tid & 31;
    const int g    = lane >> 2, t = lane & 3;
    const int wm   = (warp & 1) * 64;
    const int wn   = (warp >> 1) * 64;

    stoks[tid] = (tm + tid < ne) ? g_tok[base + tm + tid] : -1;
    __syncthreads();

    const uint32_t smem_u32 = (uint32_t)__cvta_generic_to_shared(smem);
    float* sA[2] = { smem, smem + A_STAGE };
    float* sB[2] = { smem + 2 * A_STAGE, smem + 2 * A_STAGE + B_STAGE };
    uint32_t uA[2] = { smem_u32, smem_u32 + A_STAGE * 4 };
    uint32_t uB[2] = { smem_u32 + 2 * A_STAGE * 4, smem_u32 + (2 * A_STAGE + B_STAGE) * 4 };

    float acc[4][8][4];
#pragma unroll
    for (int mf = 0; mf < 4; mf++)
#pragma unroll
        for (int nf = 0; nf < 8; nf++)
#pragma unroll
            for (int c = 0; c < 4; c++) acc[mf][nf][c] = 0.f;

    const int KIT = D_DIM / BK;  // 16

    // loader: A gathered rows, B weight rows
    auto load_tiles = [&](int kt, int st) {
        const int k0 = kt * BK;
#pragma unroll
        for (int i = 0; i < 8; i++) {          // A: 128 rows x 8 segs
            int idx = tid + i * NTHREADS;
            int r = idx >> 3, cs = (idx & 7) * 4;
            int tok = stoks[r];
            const float* src = (tok >= 0) ? &X[(size_t)tok * D_DIM + k0 + cs] : X;
            cp16(uA[st] + (r * A_STRIDE + cs) * 4, src, tok >= 0 ? 16 : 0);
        }
#pragma unroll
        for (int i = 0; i < 8; i++) {          // B: 32 rows x 32 segs
            int idx = tid + i * NTHREADS;
            int kr = idx >> 5, cs = (idx & 31) * 4;
            const float* src = &W1[((size_t)e * D_DIM + (k0 + kr)) * F_DIM + n0 + cs];
            cp16(uB[st] + (kr * B_STRIDE + cs) * 4, src, 16);
        }
        asm volatile("cp.async.commit_group;");
    };

    load_tiles(0, 0);
    for (int kt = 0; kt < KIT; kt++) {
        if (kt + 1 < KIT) {
            load_tiles(kt + 1, (kt + 1) & 1);
            asm volatile("cp.async.wait_group 1;");
        } else {
            asm volatile("cp.async.wait_group 0;");
        }
        __syncthreads();
        compute_tile(sA[kt & 1], sB[kt & 1], wm, wn, g, t, acc);
        __syncthreads();
    }

    // epilogue: bias + exact gelu -> g_H
#pragma unroll
    for (int mf = 0; mf < 4; mf++) {
#pragma unroll
        for (int nf = 0; nf < 8; nf++) {
            int row0 = wm + mf * 16 + g;
            int col  = n0 + wn + nf * 8 + t * 2;
            float b0  = B1[e * F_DIM + col];
            float b1v = B1[e * F_DIM + col + 1];
            int lr = tm + row0;
            if (lr < ne) {
                float2 h;
                h.x = gelu_exact(acc[mf][nf][0] + b0);
                h.y = gelu_exact(acc[mf][nf][1] + b1v);
                *reinterpret_cast<float2*>(&g_H[(size_t)(base + lr) * F_DIM + col]) = h;
            }
            if (lr + 8 < ne) {
                float2 h;
                h.x = gelu_exact(acc[mf][nf][2] + b0);
                h.y = gelu_exact(acc[mf][nf][3] + b1v);
                *reinterpret_cast<float2*>(&g_H[(size_t)(base + lr + 8) * F_DIM + col]) = h;
            }
        }
    }
}

// ---------------- GEMM2: out_scattered = H @ W2 + b2 ----------------
// Grid: (D/128=4, 8, 64), 128 threads
__global__ __launch_bounds__(NTHREADS) void gemm2_kernel(
    const float* __restrict__ W2, const float* __restrict__ B2, float* __restrict__ out)
{
    extern __shared__ float smem[];
    __shared__ int stoks[BM];

    const int e    = blockIdx.z;
    const int base = g_offsets[e];
    const int ne   = g_offsets[e + 1] - base;
    const int tm   = blockIdx.y * BM;
    if (tm >= ne) return;
    const int n0   = blockIdx.x * BN;

    const int tid  = threadIdx.x;
    const int warp = tid >> 5, lane = tid & 31;
    const int g    = lane >> 2, t = lane & 3;
    const int wm   = (warp & 1) * 64;
    const int wn   = (warp >> 1) * 64;

    stoks[tid] = (tm + tid < ne) ? g_tok[base + tm + tid] : -1;
    __syncthreads();

    const uint32_t smem_u32 = (uint32_t)__cvta_generic_to_shared(smem);
    float* sA[2] = { smem, smem + A_STAGE };
    float* sB[2] = { smem + 2 * A_STAGE, smem + 2 * A_STAGE + B_STAGE };
    uint32_t uA[2] = { smem_u32, smem_u32 + A_STAGE * 4 };
    uint32_t uB[2] = { smem_u32 + 2 * A_STAGE * 4, smem_u32 + (2 * A_STAGE + B_STAGE) * 4 };

    float acc[4][8][4];
#pragma unroll
    for (int mf = 0; mf < 4; mf++)
#pragma unroll
        for (int nf = 0; nf < 8; nf++)
#pragma unroll
            for (int c = 0; c < 4; c++) acc[mf][nf][c] = 0.f;

    const int KIT = F_DIM / BK;  // 64

    auto load_tiles = [&](int kt, int st) {
        const int k0 = kt * BK;
#pragma unroll
        for (int i = 0; i < 8; i++) {          // A: compact g_H rows
            int idx = tid + i * NTHREADS;
            int r = idx >> 3, cs = (idx & 7) * 4;
            bool ok = (tm + r) < ne;
            const float* src = ok ? &g_H[(size_t)(base + tm + r) * F_DIM + k0 + cs] : g_H;
            cp16(uA[st] + (r * A_STRIDE + cs) * 4, src, ok ? 16 : 0);
        }
#pragma unroll
        for (int i = 0; i < 8; i++) {
            int idx = tid + i * NTHREADS;
            int kr = idx >> 5, cs = (idx & 31) * 4;
            const float* src = &W2[((size_t)e * F_DIM + (k0 + kr)) * D_DIM + n0 + cs];
            cp16(uB[st] + (kr * B_STRIDE + cs) * 4, src, 16);
        }
        asm volatile("cp.async.commit_group;");
    };

    load_tiles(0, 0);
    for (int kt = 0; kt < KIT; kt++) {
        if (kt + 1 < KIT) {
            load_tiles(kt + 1, (kt + 1) & 1);
            asm volatile("cp.async.wait_group 1;");
        } else {
            asm volatile("cp.async.wait_group 0;");
        }
        __syncthreads();
        compute_tile(sA[kt & 1], sB[kt & 1], wm, wn, g, t, acc);
        __syncthreads();
    }

    // epilogue: bias + scatter to out[token]
#pragma unroll
    for (int mf = 0; mf < 4; mf++) {
#pragma unroll
        for (int nf = 0; nf < 8; nf++) {
            int row0 = wm + mf * 16 + g;
            int col  = n0 + wn + nf * 8 + t * 2;
            float b0  = B2[e * D_DIM + col];
            float b1v = B2[e * D_DIM + col + 1];
            int lr = tm + row0;
            if (lr < ne) {
                int tok = stoks[row0];
                float2 o;
                o.x = acc[mf][nf][0] + b0;
                o.y = acc[mf][nf][1] + b1v;
                *reinterpret_cast<float2*>(&out[(size_t)tok * D_DIM + col]) = o;
            }
            if (lr + 8 < ne) {
                int tok = stoks[row0 + 8];
                float2 o;
                o.x = acc[mf][nf][2] + b0;
                o.y = acc[mf][nf][3] + b1v;
                *reinterpret_cast<float2*>(&out[(size_t)tok * D_DIM + col]) = o;
            }
        }
    }
}

// ---------------- launch ----------------
extern "C" void kernel_launch(void* const* d_in, const int* in_sizes, int n_in,
                              void* d_out, int out_size)
{
    const float* X    = (const float*)d_in[0];
    const int*   disp = (const int*)d_in[1];
    const float* W1   = (const float*)d_in[2];
    const float* B1   = (const float*)d_in[3];
    const float* W2   = (const float*)d_in[4];
    const float* B2   = (const float*)d_in[5];
    float*       out  = (float*)d_out;

    cudaFuncSetAttribute(gemm1_kernel, cudaFuncAttributeMaxDynamicSharedMemorySize, SMEM_BYTES);
    cudaFuncSetAttribute(gemm2_kernel, cudaFuncAttributeMaxDynamicSharedMemorySize, SMEM_BYTES);

    init_kernel<<<1, 64>>>();
    count_kernel<<<T_TOKENS / 256, 256>>>(disp);
    scan_kernel<<<1, 1>>>();
    fill_kernel<<<T_TOKENS / 256, 256>>>(disp);
    gemm1_kernel<<<dim3(F_DIM / 128, 8, N_EXP), NTHREADS, SMEM_BYTES>>>(X, W1, B1);
    gemm2_kernel<<<dim3(D_DIM / 128, 8, N_EXP), NTHREADS, SMEM_BYTES>>>(W2, B2, out);
}

// round 10
// speedup vs baseline: 2.1574x; 1.6961x over previous
#include <cuda_runtime.h>
#include <cuda_fp16.h>
#include <cstdint>

#define T_TOKENS 32768
#define D_DIM    512
#define F_DIM    2048
#define N_EXP    64

#define BM 128
#define BN 128
#define BK 32
#define NTH 128

// smem geometry (bank-conflict-engineered strides)
#define A_ROW_B   80                      // 32 halves + pad -> banks 20r%32, LDSM conflict-free
#define B_ROW_B   272                     // 128 halves + pad -> banks 4k%32, LDSM.T conflict-free
#define A_STAGE_B (BM * A_ROW_B)          // 10240
#define B_STAGE_B (BK * B_ROW_B)          // 8704
#define A_STAGES  3
#define B_STAGES  2
#define DSMEM_B   (A_STAGES * A_STAGE_B + B_STAGES * B_STAGE_B)   // 48128

// ---------------- device scratch ----------------
__device__ int    g_counts[N_EXP];
__device__ int    g_offsets[N_EXP + 1];
__device__ int    g_fill[N_EXP];
__device__ int    g_tok[T_TOKENS];
__device__ __half g_Xh[(size_t)T_TOKENS * D_DIM];   // 32 MB  fp16 inputs
__device__ __half g_Hh[(size_t)T_TOKENS * F_DIM];   // 128 MB fp16 intermediate

// ---------------- helpers ----------------
__device__ __forceinline__ float gelu_exact(float x) {
    return 0.5f * x * (1.0f + erff(x * 0.70710678118654752f));
}

__device__ __forceinline__ uint32_t smem_u32(const void* p) {
    uint32_t a;
    asm("{ .reg .u64 t; cvta.to.shared.u64 t, %1; cvt.u32.u64 %0, t; }" : "=r"(a) : "l"(p));
    return a;
}

__device__ __forceinline__ void cp16(uint32_t dst, const void* src, int szbytes) {
    asm volatile("cp.async.cg.shared.global [%0], [%1], 16, %2;"
                 :: "r"(dst), "l"(src), "r"(szbytes));
}
#define CP_COMMIT() asm volatile("cp.async.commit_group;")

#define LDSM_X4(r, addr) \
    asm volatile("ldmatrix.sync.aligned.m8n8.x4.shared.b16 {%0,%1,%2,%3}, [%4];" \
        : "=r"((r)[0]), "=r"((r)[1]), "=r"((r)[2]), "=r"((r)[3]) : "r"(addr))

#define LDSM_X4_T(r0, r1, r2, r3, addr) \
    asm volatile("ldmatrix.sync.aligned.m8n8.x4.trans.shared.b16 {%0,%1,%2,%3}, [%4];" \
        : "=r"(r0), "=r"(r1), "=r"(r2), "=r"(r3) : "r"(addr))

__device__ __forceinline__ void mma_f16(float* c, const uint32_t* a, const uint32_t* b) {
    asm volatile(
        "mma.sync.aligned.m16n8k16.row.col.f32.f16.f16.f32 "
        "{%0,%1,%2,%3}, {%4,%5,%6,%7}, {%8,%9}, {%0,%1,%2,%3};"
        : "+f"(c[0]), "+f"(c[1]), "+f"(c[2]), "+f"(c[3])
        : "r"(a[0]), "r"(a[1]), "r"(a[2]), "r"(a[3]), "r"(b[0]), "r"(b[1]));
}

__device__ __forceinline__ uint32_t pack_h2(float lo, float hi) {
    uint32_t d;
    asm("cvt.rn.f16x2.f32 %0, %1, %2;" : "=r"(d) : "f"(hi), "f"(lo));  // first src -> upper
    return d;
}

// ---------------- bookkeeping ----------------
__global__ void init_kernel() {
    int i = threadIdx.x;
    if (i < N_EXP) { g_counts[i] = 0; g_fill[i] = 0; }
}
__global__ void count_kernel(const int* __restrict__ disp) {
    int t = blockIdx.x * blockDim.x + threadIdx.x;
    if (t < T_TOKENS) atomicAdd(&g_counts[disp[t]], 1);
}
__global__ void scan_kernel() {
    if (threadIdx.x == 0) {
        int s = 0;
        for (int i = 0; i < N_EXP; i++) { g_offsets[i] = s; s += g_counts[i]; }
        g_offsets[N_EXP] = s;
    }
}
__global__ void fill_kernel(const int* __restrict__ disp) {
    int t = blockIdx.x * blockDim.x + threadIdx.x;
    if (t < T_TOKENS) {
        int e = disp[t];
        int p = atomicAdd(&g_fill[e], 1);
        g_tok[g_offsets[e] + p] = t;
    }
}

// ---------------- X conversion: fp32 -> fp16 ----------------
__global__ void convert_x_kernel(const float* __restrict__ X) {
    size_t i = ((size_t)blockIdx.x * 256 + threadIdx.x) * 8;
    float4 v0 = *reinterpret_cast<const float4*>(&X[i]);
    float4 v1 = *reinterpret_cast<const float4*>(&X[i + 4]);
    uint4 o;
    o.x = pack_h2(v0.x, v0.y); o.y = pack_h2(v0.z, v0.w);
    o.z = pack_h2(v1.x, v1.y); o.w = pack_h2(v1.z, v1.w);
    *reinterpret_cast<uint4*>(&g_Hh[0] + 0) = o;  // placeholder, replaced below
}

// (real converter — writes g_Xh)
__global__ void convert_x2_kernel(const float* __restrict__ X) {
    size_t i = ((size_t)blockIdx.x * 256 + threadIdx.x) * 8;
    float4 v0 = *reinterpret_cast<const float4*>(&X[i]);
    float4 v1 = *reinterpret_cast<const float4*>(&X[i + 4]);
    uint4 o;
    o.x = pack_h2(v0.x, v0.y); o.y = pack_h2(v0.z, v0.w);
    o.z = pack_h2(v1.x, v1.y); o.w = pack_h2(v1.z, v1.w);
    *reinterpret_cast<uint4*>(&g_Xh[i]) = o;
}

// ================= GEMM kernels (fp16 HMMA m16n8k16) =================
// 128 threads = 4 warps (2x2), warp tile 64x64. A: cp.async fp16 3-stage.
// B: fp32 LDG -> cvt -> STS fp16, register double-buffered, 2-stage smem.

// ---- GEMM1: H = gelu(Xh_gathered @ W1 + b1) -> g_Hh. Grid (16, 8, 64). ----
__global__ __launch_bounds__(NTH, 2) void gemm1_kernel(
    const float* __restrict__ W1, const float* __restrict__ B1)
{
    extern __shared__ char dsm[];
    __shared__ int   stoks[BM];
    __shared__ float sbias[BN];

    const int e    = blockIdx.z;
    const int base = g_offsets[e];
    const int ne   = g_offsets[e + 1] - base;
    const int tm   = blockIdx.y * BM;
    if (tm >= ne) return;
    const int n0   = blockIdx.x * BN;

    const int tid  = threadIdx.x;
    const int warp = tid >> 5, lane = tid & 31;
    const int wm   = (warp & 1) * 64;
    const int wn   = (warp >> 1) * 64;

    stoks[tid] = (tm + tid < ne) ? g_tok[base + tm + tid] : -1;
    sbias[tid] = B1[e * F_DIM + n0 + tid];

    const uint32_t sb = smem_u32(dsm);
    uint32_t uA[A_STAGES], uB[B_STAGES];
#pragma unroll
    for (int s = 0; s < A_STAGES; s++) uA[s] = sb + s * A_STAGE_B;
#pragma unroll
    for (int s = 0; s < B_STAGES; s++) uB[s] = sb + A_STAGES * A_STAGE_B + s * B_STAGE_B;

    float acc[4][8][4];
#pragma unroll
    for (int mf = 0; mf < 4; mf++)
#pragma unroll
        for (int nf = 0; nf < 8; nf++)
#pragma unroll
            for (int c = 0; c < 4; c++) acc[mf][nf][c] = 0.f;

    const int KIT = D_DIM / BK;            // 16
    const int kr = tid >> 2, q = tid & 3;  // B-loader mapping

    // prologue: B(0) LDG
    float4 b4[8];
    {
        const float* wrow = &W1[((size_t)e * D_DIM + kr) * F_DIM + n0];
#pragma unroll
        for (int j = 0; j < 8; j++) b4[j] = *reinterpret_cast<const float4*>(wrow + q * 4 + j * 16);
    }
    __syncthreads();   // stoks visible

    // A loader (call order defines cp.async group order)
    auto loadA = [&](int kt) {
        const int k0 = kt * BK;
        const uint32_t ua = uA[kt % A_STAGES];
#pragma unroll
        for (int i = 0; i < 4; i++) {
            int idx = tid + i * NTH;
            int r = idx >> 2, cc = idx & 3;
            int tok = stoks[r];
            const __half* src = (tok >= 0) ? &g_Xh[(size_t)tok * D_DIM + k0 + cc * 8] : g_Xh;
            cp16(ua + r * A_ROW_B + cc * 16, src, tok >= 0 ? 16 : 0);
        }
        CP_COMMIT();
    };

    loadA(0);
    if (KIT > 1) loadA(1);

    // prologue: B(0) cvt+STS -> stage 0
    {
        uint32_t ub = uB[0] + kr * B_ROW_B + q * 8;
#pragma unroll
        for (int j = 0; j < 8; j++) {
            uint32_t h0 = pack_h2(b4[j].x, b4[j].y);
            uint32_t h1 = pack_h2(b4[j].z, b4[j].w);
            asm volatile("st.shared.v2.b32 [%0], {%1,%2};" :: "r"(ub + j * 32), "r"(h0), "r"(h1));
        }
    }

    for (int kt = 0; kt < KIT; kt++) {
        // (a) issue B LDG for kt+1
        if (kt + 1 < KIT) {
            const float* wrow = &W1[((size_t)e * D_DIM + ((kt + 1) * BK + kr)) * F_DIM + n0];
#pragma unroll
            for (int j = 0; j < 8; j++) b4[j] = *reinterpret_cast<const float4*>(wrow + q * 4 + j * 16);
        }
        // (b) wait A(kt), barrier (also publishes B stage STS from last iter)
        if (kt + 1 < KIT) { asm volatile("cp.async.wait_group 1;"); }
        else              { asm volatile("cp.async.wait_group 0;"); }
        __syncthreads();
        // (c) prefetch A(kt+2)
        if (kt + 2 < KIT) loadA(kt + 2);
        // (d) compute tile kt
        {
            const uint32_t ua = uA[kt % A_STAGES];
            const uint32_t ub = uB[kt % B_STAGES];
#pragma unroll
            for (int c = 0; c < 2; c++) {
                uint32_t a[4][4];
#pragma unroll
                for (int mf = 0; mf < 4; mf++) {
                    int row = wm + mf * 16 + (lane & 7) + ((lane >> 3) & 1) * 8;
                    LDSM_X4(a[mf], ua + row * A_ROW_B + ((lane >> 4) + 2 * c) * 16);
                }
                uint32_t b[8][2];
#pragma unroll
                for (int p = 0; p < 4; p++) {
                    int k = c * 16 + ((lane >> 3) & 1) * 8 + (lane & 7);
                    int n = wn + p * 16 + (lane >> 4) * 8;
                    uint32_t r0, r1, r2, r3;
                    LDSM_X4_T(r0, r1, r2, r3, ub + k * B_ROW_B + n * 2);
                    b[2 * p][0] = r0; b[2 * p][1] = r1;
                    b[2 * p + 1][0] = r2; b[2 * p + 1][1] = r3;
                }
#pragma unroll
                for (int mf = 0; mf < 4; mf++)
#pragma unroll
                    for (int nf = 0; nf < 8; nf++)
                        mma_f16(acc[mf][nf], a[mf], b[nf]);
            }
        }
        // (e) B(kt+1) cvt+STS -> stage (kt+1)%2  (stage free: barrier (b) passed)
        if (kt + 1 < KIT) {
            uint32_t ub = uB[(kt + 1) % B_STAGES] + kr * B_ROW_B + q * 8;
#pragma unroll
            for (int j = 0; j < 8; j++) {
                uint32_t h0 = pack_h2(b4[j].x, b4[j].y);
                uint32_t h1 = pack_h2(b4[j].z, b4[j].w);
                asm volatile("st.shared.v2.b32 [%0], {%1,%2};" :: "r"(ub + j * 32), "r"(h0), "r"(h1));
            }
        }
    }

    // epilogue: bias + exact gelu -> fp16 g_Hh
    const int g = lane >> 2, t2 = lane & 3;
#pragma unroll
    for (int mf = 0; mf < 4; mf++) {
#pragma unroll
        for (int nf = 0; nf < 8; nf++) {
            int row0 = wm + mf * 16 + g;
            int colL = wn + nf * 8 + t2 * 2;
            float b0 = sbias[colL], b1 = sbias[colL + 1];
            int lr = tm + row0;
            if (lr < ne) {
                uint32_t h = pack_h2(gelu_exact(acc[mf][nf][0] + b0),
                                     gelu_exact(acc[mf][nf][1] + b1));
                *reinterpret_cast<uint32_t*>(&g_Hh[(size_t)(base + lr) * F_DIM + n0 + colL]) = h;
            }
            if (lr + 8 < ne) {
                uint32_t h = pack_h2(gelu_exact(acc[mf][nf][2] + b0),
                                     gelu_exact(acc[mf][nf][3] + b1));
                *reinterpret_cast<uint32_t*>(&g_Hh[(size_t)(base + lr + 8) * F_DIM + n0 + colL]) = h;
            }
        }
    }
}

// ---- GEMM2: out = Hh @ W2 + b2, scattered fp32. Grid (4, 8, 64). ----
__global__ __launch_bounds__(NTH, 2) void gemm2_kernel(
    const float* __restrict__ W2, const float* __restrict__ B2, float* __restrict__ out)
{
    extern __shared__ char dsm[];
    __shared__ int   stoks[BM];
    __shared__ float sbias[BN];

    const int e    = blockIdx.z;
    const int base = g_offsets[e];
    const int ne   = g_offsets[e + 1] - base;
    const int tm   = blockIdx.y * BM;
    if (tm >= ne) return;
    const int n0   = blockIdx.x * BN;

    const int tid  = threadIdx.x;
    const int warp = tid >> 5, lane = tid & 31;
    const int wm   = (warp & 1) * 64;
    const int wn   = (warp >> 1) * 64;

    stoks[tid] = (tm + tid < ne) ? g_tok[base + tm + tid] : -1;
    sbias[tid] = B2[e * D_DIM + n0 + tid];

    const uint32_t sb = smem_u32(dsm);
    uint32_t uA[A_STAGES], uB[B_STAGES];
#pragma unroll
    for (int s = 0; s < A_STAGES; s++) uA[s] = sb + s * A_STAGE_B;
#pragma unroll
    for (int s = 0; s < B_STAGES; s++) uB[s] = sb + A_STAGES * A_STAGE_B + s * B_STAGE_B;

    float acc[4][8][4];
#pragma unroll
    for (int mf = 0; mf < 4; mf++)
#pragma unroll
        for (int nf = 0; nf < 8; nf++)
#pragma unroll
            for (int c = 0; c < 4; c++) acc[mf][nf][c] = 0.f;

    const int KIT = F_DIM / BK;            // 64
    const int kr = tid >> 2, q = tid & 3;

    float4 b4[8];
    {
        const float* wrow = &W2[((size_t)e * F_DIM + kr) * D_DIM + n0];
#pragma unroll
        for (int j = 0; j < 8; j++) b4[j] = *reinterpret_cast<const float4*>(wrow + q * 4 + j * 16);
    }
    __syncthreads();

    auto loadA = [&](int kt) {
        const int k0 = kt * BK;
        const uint32_t ua = uA[kt % A_STAGES];
#pragma unroll
        for (int i = 0; i < 4; i++) {
            int idx = tid + i * NTH;
            int r = idx >> 2, cc = idx & 3;
            bool ok = (tm + r) < ne;
            const __half* src = ok ? &g_Hh[(size_t)(base + tm + r) * F_DIM + k0 + cc * 8] : g_Hh;
            cp16(ua + r * A_ROW_B + cc * 16, src, ok ? 16 : 0);
        }
        CP_COMMIT();
    };

    loadA(0);
    loadA(1);

    {
        uint32_t ub = uB[0] + kr * B_ROW_B + q * 8;
#pragma unroll
        for (int j = 0; j < 8; j++) {
            uint32_t h0 = pack_h2(b4[j].x, b4[j].y);
            uint32_t h1 = pack_h2(b4[j].z, b4[j].w);
            asm volatile("st.shared.v2.b32 [%0], {%1,%2};" :: "r"(ub + j * 32), "r"(h0), "r"(h1));
        }
    }

    for (int kt = 0; kt < KIT; kt++) {
        if (kt + 1 < KIT) {
            const float* wrow = &W2[((size_t)e * F_DIM + ((kt + 1) * BK + kr)) * D_DIM + n0];
#pragma unroll
            for (int j = 0; j < 8; j++) b4[j] = *reinterpret_cast<const float4*>(wrow + q * 4 + j * 16);
        }
        if (kt + 1 < KIT) { asm volatile("cp.async.wait_group 1;"); }
        else              { asm volatile("cp.async.wait_group 0;"); }
        __syncthreads();
        if (kt + 2 < KIT) loadA(kt + 2);
        {
            const uint32_t ua = uA[kt % A_STAGES];
            const uint32_t ub = uB[kt % B_STAGES];
#pragma unroll
            for (int c = 0; c < 2; c++) {
                uint32_t a[4][4];
#pragma unroll
                for (int mf = 0; mf < 4; mf++) {
                    int row = wm + mf * 16 + (lane & 7) + ((lane >> 3) & 1) * 8;
                    LDSM_X4(a[mf], ua + row * A_ROW_B + ((lane >> 4) + 2 * c) * 16);
                }
                uint32_t b[8][2];
#pragma unroll
                for (int p = 0; p < 4; p++) {
                    int k = c * 16 + ((lane >> 3) & 1) * 8 + (lane & 7);
                    int n = wn + p * 16 + (lane >> 4) * 8;
                    uint32_t r0, r1, r2, r3;
                    LDSM_X4_T(r0, r1, r2, r3, ub + k * B_ROW_B + n * 2);
                    b[2 * p][0] = r0; b[2 * p][1] = r1;
                    b[2 * p + 1][0] = r2; b[2 * p + 1][1] = r3;
                }
#pragma unroll
                for (int mf = 0; mf < 4; mf++)
#pragma unroll
                    for (int nf = 0; nf < 8; nf++)
                        mma_f16(acc[mf][nf], a[mf], b[nf]);
            }
        }
        if (kt + 1 < KIT) {
            uint32_t ub = uB[(kt + 1) % B_STAGES] + kr * B_ROW_B + q * 8;
#pragma unroll
            for (int j = 0; j < 8; j++) {
                uint32_t h0 = pack_h2(b4[j].x, b4[j].y);
                uint32_t h1 = pack_h2(b4[j].z, b4[j].w);
                asm volatile("st.shared.v2.b32 [%0], {%1,%2};" :: "r"(ub + j * 32), "r"(h0), "r"(h1));
            }
        }
    }

    // epilogue: bias + scatter fp32
    const int g = lane >> 2, t2 = lane & 3;
#pragma unroll
    for (int mf = 0; mf < 4; mf++) {
#pragma unroll
        for (int nf = 0; nf < 8; nf++) {
            int row0 = wm + mf * 16 + g;
            int colL = wn + nf * 8 + t2 * 2;
            float b0 = sbias[colL], b1 = sbias[colL + 1];
            int lr = tm + row0;
            if (lr < ne) {
                int tok = stoks[row0];
                float2 o = make_float2(acc[mf][nf][0] + b0, acc[mf][nf][1] + b1);
                *reinterpret_cast<float2*>(&out[(size_t)tok * D_DIM + n0 + colL]) = o;
            }
            if (lr + 8 < ne) {
                int tok = stoks[row0 + 8];
                float2 o = make_float2(acc[mf][nf][2] + b0, acc[mf][nf][3] + b1);
                *reinterpret_cast<float2*>(&out[(size_t)tok * D_DIM + n0 + colL]) = o;
            }
        }
    }
}

// ---------------- launch ----------------
extern "C" void kernel_launch(void* const* d_in, const int* in_sizes, int n_in,
                              void* d_out, int out_size)
{
    const float* X    = (const float*)d_in[0];
    const int*   disp = (const int*)d_in[1];
    const float* W1   = (const float*)d_in[2];
    const float* B1   = (const float*)d_in[3];
    const float* W2   = (const float*)d_in[4];
    const float* B2   = (const float*)d_in[5];
    float*       out  = (float*)d_out;

    cudaFuncSetAttribute(gemm1_kernel, cudaFuncAttributeMaxDynamicSharedMemorySize, DSMEM_B);
    cudaFuncSetAttribute(gemm2_kernel, cudaFuncAttributeMaxDynamicSharedMemorySize, DSMEM_B);

    init_kernel<<<1, 64>>>();
    count_kernel<<<T_TOKENS / 256, 256>>>(disp);
    scan_kernel<<<1, 1>>>();
    fill_kernel<<<T_TOKENS / 256, 256>>>(disp);
    convert_x2_kernel<<<(T_TOKENS * D_DIM) / (256 * 8), 256>>>(X);
    gemm1_kernel<<<dim3(F_DIM / BN, 8, N_EXP), NTH, DSMEM_B>>>(W1, B1);
    gemm2_kernel<<<dim3(D_DIM / BN, 8, N_EXP), NTH, DSMEM_B>>>(W2, B2, out);
}

// round 11
// speedup vs baseline: 2.2396x; 1.0381x over previous
#include <cuda_runtime.h>
#include <cuda_fp16.h>
#include <cstdint>

#define T_TOKENS 32768
#define D_DIM    512
#define F_DIM    2048
#define N_EXP    64

#define BM 128
#define BN 128
#define BK 32
#define NTH 128

// smem geometry (bank-conflict-engineered strides)
#define A_ROW_B   80                      // 32 halves + pad -> banks 20r%32, LDSM conflict-free
#define B_ROW_B   272                     // 128 halves + pad -> banks 4k%32, LDSM.T conflict-free
#define A_STAGE_B (BM * A_ROW_B)          // 10240
#define B_STAGE_B (BK * B_ROW_B)          // 8704
#define STAGES    3
#define DSMEM_B   (STAGES * (A_STAGE_B + B_STAGE_B))   // 56832 -> 2 CTAs/SM

// ---------------- device scratch ----------------
__device__ int    g_offsets[N_EXP + 1];
__device__ int    g_tok[T_TOKENS];
__device__ __half g_Xg [(size_t)T_TOKENS * D_DIM];   // 32 MB  fp16 X, expert-gathered order
__device__ __half g_Hh [(size_t)T_TOKENS * F_DIM];   // 128 MB fp16 intermediate (compact)
__device__ __half g_W1h[(size_t)N_EXP * D_DIM * F_DIM];  // 134 MB
__device__ __half g_W2h[(size_t)N_EXP * F_DIM * D_DIM];  // 134 MB

// ---------------- helpers ----------------
__device__ __forceinline__ float gelu_exact(float x) {
    return 0.5f * x * (1.0f + erff(x * 0.70710678118654752f));
}

__device__ __forceinline__ uint32_t smem_u32(const void* p) {
    uint32_t a;
    asm("{ .reg .u64 t; cvta.to.shared.u64 t, %1; cvt.u32.u64 %0, t; }" : "=r"(a) : "l"(p));
    return a;
}

__device__ __forceinline__ void cp16(uint32_t dst, const void* src) {
    asm volatile("cp.async.cg.shared.global [%0], [%1], 16;" :: "r"(dst), "l"(src));
}
#define CP_COMMIT() asm volatile("cp.async.commit_group;")

#define LDSM_X4(r, addr) \
    asm volatile("ldmatrix.sync.aligned.m8n8.x4.shared.b16 {%0,%1,%2,%3}, [%4];" \
        : "=r"((r)[0]), "=r"((r)[1]), "=r"((r)[2]), "=r"((r)[3]) : "r"(addr))

#define LDSM_X4_T(r0, r1, r2, r3, addr) \
    asm volatile("ldmatrix.sync.aligned.m8n8.x4.trans.shared.b16 {%0,%1,%2,%3}, [%4];" \
        : "=r"(r0), "=r"(r1), "=r"(r2), "=r"(r3) : "r"(addr))

__device__ __forceinline__ void mma_f16(float* c, const uint32_t* a, const uint32_t* b) {
    asm volatile(
        "mma.sync.aligned.m16n8k16.row.col.f32.f16.f16.f32 "
        "{%0,%1,%2,%3}, {%4,%5,%6,%7}, {%8,%9}, {%0,%1,%2,%3};"
        : "+f"(c[0]), "+f"(c[1]), "+f"(c[2]), "+f"(c[3])
        : "r"(a[0]), "r"(a[1]), "r"(a[2]), "r"(a[3]), "r"(b[0]), "r"(b[1]));
}

__device__ __forceinline__ uint32_t pack_h2(float lo, float hi) {
    uint32_t d;
    asm("cvt.rn.f16x2.f32 %0, %1, %2;" : "=r"(d) : "f"(hi), "f"(lo));  // first src -> upper
    return d;
}

// ---------------- fused dispatch (one CTA) ----------------
__global__ void dispatch_kernel(const int* __restrict__ disp) {
    __shared__ int cnt[N_EXP];
    __shared__ int off[N_EXP];
    const int tid = threadIdx.x;                 // 1024 threads
    if (tid < N_EXP) cnt[tid] = 0;
    __syncthreads();
    for (int t = tid; t < T_TOKENS; t += 1024) atomicAdd(&cnt[disp[t]], 1);
    __syncthreads();
    if (tid == 0) {
        int s = 0;
        for (int e = 0; e < N_EXP; e++) { off[e] = s; g_offsets[e] = s; s += cnt[e]; }
        g_offsets[N_EXP] = s;
    }
    __syncthreads();
    if (tid < N_EXP) cnt[tid] = 0;               // reuse as cursors
    __syncthreads();
    for (int t = tid; t < T_TOKENS; t += 1024) {
        int e = disp[t];
        int p = atomicAdd(&cnt[e], 1);
        g_tok[off[e] + p] = t;
    }
}

// ---------------- gather + convert X: g_Xg[slot] = fp16(X[g_tok[slot]]) ----------------
__global__ void gather_x_kernel(const float* __restrict__ X) {
    const int slot  = blockIdx.x * 2 + (threadIdx.x >> 7);
    const int local = threadIdx.x & 127;
    const int tok   = g_tok[slot];
    float4 v = *reinterpret_cast<const float4*>(&X[(size_t)tok * D_DIM + local * 4]);
    uint2 o;
    o.x = pack_h2(v.x, v.y); o.y = pack_h2(v.z, v.w);
    *reinterpret_cast<uint2*>(&g_Xg[(size_t)slot * D_DIM + local * 4]) = o;
}

// ---------------- W fp32 -> fp16 ----------------
__global__ void convert_w_kernel(const float* __restrict__ W, __half* __restrict__ Wh) {
    size_t i = ((size_t)blockIdx.x * 256 + threadIdx.x) * 8;
    float4 v0 = *reinterpret_cast<const float4*>(&W[i]);
    float4 v1 = *reinterpret_cast<const float4*>(&W[i + 4]);
    uint4 o;
    o.x = pack_h2(v0.x, v0.y); o.y = pack_h2(v0.z, v0.w);
    o.z = pack_h2(v1.x, v1.y); o.w = pack_h2(v1.z, v1.w);
    *reinterpret_cast<uint4*>(&Wh[i]) = o;
}

// ================= GEMM kernels (fp16 HMMA, dual-operand 3-stage cp.async) =================
// 128 threads = 4 warps (2x2), warp tile 64x64, one __syncthreads per K-tile.

// ---- GEMM1: H = gelu(Xg @ W1h + b1) -> g_Hh (compact). Grid (16, 8, 64). ----
__global__ __launch_bounds__(NTH, 2) void gemm1_kernel(const float* __restrict__ B1)
{
    extern __shared__ char dsm[];
    __shared__ float sbias[BN];

    const int e    = blockIdx.z;
    const int base = g_offsets[e];
    const int ne   = g_offsets[e + 1] - base;
    const int tm   = blockIdx.y * BM;
    if (tm >= ne) return;
    const int n0   = blockIdx.x * BN;

    const int tid  = threadIdx.x;
    const int warp = tid >> 5, lane = tid & 31;
    const int wm   = (warp & 1) * 64;
    const int wn   = (warp >> 1) * 64;

    sbias[tid] = B1[e * F_DIM + n0 + tid];

    const uint32_t sb = smem_u32(dsm);
    uint32_t uA[STAGES], uB[STAGES];
#pragma unroll
    for (int s = 0; s < STAGES; s++) {
        uA[s] = sb + s * A_STAGE_B;
        uB[s] = sb + STAGES * A_STAGE_B + s * B_STAGE_B;
    }

    float acc[4][8][4];
#pragma unroll
    for (int mf = 0; mf < 4; mf++)
#pragma unroll
        for (int nf = 0; nf < 8; nf++)
#pragma unroll
            for (int c = 0; c < 4; c++) acc[mf][nf][c] = 0.f;

    const int KIT = D_DIM / BK;  // 16

    auto load_stage = [&](int kt) {
        const int k0 = kt * BK;
        const int s  = kt % STAGES;
#pragma unroll
        for (int i = 0; i < 4; i++) {                        // A: 128 rows x 4 segs
            int idx = tid + i * NTH;
            int r = idx >> 2, cc = idx & 3;
            int arow = base + tm + r; if (arow > T_TOKENS - 1) arow = T_TOKENS - 1;
            cp16(uA[s] + r * A_ROW_B + cc * 16, &g_Xg[(size_t)arow * D_DIM + k0 + cc * 8]);
        }
#pragma unroll
        for (int i = 0; i < 4; i++) {                        // B: 32 k-rows x 16 segs
            int idx = tid + i * NTH;
            int kr = idx >> 4, seg = idx & 15;
            cp16(uB[s] + kr * B_ROW_B + seg * 16,
                 &g_W1h[((size_t)e * D_DIM + k0 + kr) * F_DIM + n0 + seg * 8]);
        }
        CP_COMMIT();
    };

    load_stage(0);
    load_stage(1);

    for (int kt = 0; kt < KIT; kt++) {
        if (kt + 1 < KIT) { asm volatile("cp.async.wait_group 1;"); }
        else              { asm volatile("cp.async.wait_group 0;"); }
        __syncthreads();
        if (kt + 2 < KIT) load_stage(kt + 2);
        const uint32_t ua = uA[kt % STAGES];
        const uint32_t ub = uB[kt % STAGES];
#pragma unroll
        for (int c = 0; c < 2; c++) {
            uint32_t a[4][4];
#pragma unroll
            for (int mf = 0; mf < 4; mf++) {
                int row = wm + mf * 16 + (lane & 7) + ((lane >> 3) & 1) * 8;
                LDSM_X4(a[mf], ua + row * A_ROW_B + ((lane >> 4) + 2 * c) * 16);
            }
            uint32_t b[8][2];
#pragma unroll
            for (int p = 0; p < 4; p++) {
                int k = c * 16 + ((lane >> 3) & 1) * 8 + (lane & 7);
                int n = wn + p * 16 + (lane >> 4) * 8;
                uint32_t r0, r1, r2, r3;
                LDSM_X4_T(r0, r1, r2, r3, ub + k * B_ROW_B + n * 2);
                b[2 * p][0] = r0; b[2 * p][1] = r1;
                b[2 * p + 1][0] = r2; b[2 * p + 1][1] = r3;
            }
#pragma unroll
            for (int mf = 0; mf < 4; mf++)
#pragma unroll
                for (int nf = 0; nf < 8; nf++)
                    mma_f16(acc[mf][nf], a[mf], b[nf]);
        }
    }

    // epilogue: bias + exact gelu -> fp16 g_Hh (compact rows)
    const int g = lane >> 2, t2 = lane & 3;
#pragma unroll
    for (int mf = 0; mf < 4; mf++) {
#pragma unroll
        for (int nf = 0; nf < 8; nf++) {
            int row0 = wm + mf * 16 + g;
            int colL = wn + nf * 8 + t2 * 2;
            float b0 = sbias[colL], b1 = sbias[colL + 1];
            int lr = tm + row0;
            if (lr < ne) {
                uint32_t h = pack_h2(gelu_exact(acc[mf][nf][0] + b0),
                                     gelu_exact(acc[mf][nf][1] + b1));
                *reinterpret_cast<uint32_t*>(&g_Hh[(size_t)(base + lr) * F_DIM + n0 + colL]) = h;
            }
            if (lr + 8 < ne) {
                uint32_t h = pack_h2(gelu_exact(acc[mf][nf][2] + b0),
                                     gelu_exact(acc[mf][nf][3] + b1));
                *reinterpret_cast<uint32_t*>(&g_Hh[(size_t)(base + lr + 8) * F_DIM + n0 + colL]) = h;
            }
        }
    }
}

// ---- GEMM2: out = Hh @ W2h + b2, scattered fp32. Grid (4, 8, 64). ----
__global__ __launch_bounds__(NTH, 2) void gemm2_kernel(const float* __restrict__ B2,
                                                       float* __restrict__ out)
{
    extern __shared__ char dsm[];
    __shared__ int   stoks[BM];
    __shared__ float sbias[BN];

    const int e    = blockIdx.z;
    const int base = g_offsets[e];
    const int ne   = g_offsets[e + 1] - base;
    const int tm   = blockIdx.y * BM;
    if (tm >= ne) return;
    const int n0   = blockIdx.x * BN;

    const int tid  = threadIdx.x;
    const int warp = tid >> 5, lane = tid & 31;
    const int wm   = (warp & 1) * 64;
    const int wn   = (warp >> 1) * 64;

    stoks[tid] = (tm + tid < ne) ? g_tok[base + tm + tid] : -1;
    sbias[tid] = B2[e * D_DIM + n0 + tid];

    const uint32_t sb = smem_u32(dsm);
    uint32_t uA[STAGES], uB[STAGES];
#pragma unroll
    for (int s = 0; s < STAGES; s++) {
        uA[s] = sb + s * A_STAGE_B;
        uB[s] = sb + STAGES * A_STAGE_B + s * B_STAGE_B;
    }

    float acc[4][8][4];
#pragma unroll
    for (int mf = 0; mf < 4; mf++)
#pragma unroll
        for (int nf = 0; nf < 8; nf++)
#pragma unroll
            for (int c = 0; c < 4; c++) acc[mf][nf][c] = 0.f;

    const int KIT = F_DIM / BK;  // 64

    auto load_stage = [&](int kt) {
        const int k0 = kt * BK;
        const int s  = kt % STAGES;
#pragma unroll
        for (int i = 0; i < 4; i++) {
            int idx = tid + i * NTH;
            int r = idx >> 2, cc = idx & 3;
            int arow = base + tm + r; if (arow > T_TOKENS - 1) arow = T_TOKENS - 1;
            cp16(uA[s] + r * A_ROW_B + cc * 16, &g_Hh[(size_t)arow * F_DIM + k0 + cc * 8]);
        }
#pragma unroll
        for (int i = 0; i < 4; i++) {
            int idx = tid + i * NTH;
            int kr = idx >> 4, seg = idx & 15;
            cp16(uB[s] + kr * B_ROW_B + seg * 16,
                 &g_W2h[((size_t)e * F_DIM + k0 + kr) * D_DIM + n0 + seg * 8]);
        }
        CP_COMMIT();
    };

    load_stage(0);
    load_stage(1);

    for (int kt = 0; kt < KIT; kt++) {
        if (kt + 1 < KIT) { asm volatile("cp.async.wait_group 1;"); }
        else              { asm volatile("cp.async.wait_group 0;"); }
        __syncthreads();
        if (kt + 2 < KIT) load_stage(kt + 2);
        const uint32_t ua = uA[kt % STAGES];
        const uint32_t ub = uB[kt % STAGES];
#pragma unroll
        for (int c = 0; c < 2; c++) {
            uint32_t a[4][4];
#pragma unroll
            for (int mf = 0; mf < 4; mf++) {
                int row = wm + mf * 16 + (lane & 7) + ((lane >> 3) & 1) * 8;
                LDSM_X4(a[mf], ua + row * A_ROW_B + ((lane >> 4) + 2 * c) * 16);
            }
            uint32_t b[8][2];
#pragma unroll
            for (int p = 0; p < 4; p++) {
                int k = c * 16 + ((lane >> 3) & 1) * 8 + (lane & 7);
                int n = wn + p * 16 + (lane >> 4) * 8;
                uint32_t r0, r1, r2, r3;
                LDSM_X4_T(r0, r1, r2, r3, ub + k * B_ROW_B + n * 2);
                b[2 * p][0] = r0; b[2 * p][1] = r1;
                b[2 * p + 1][0] = r2; b[2 * p + 1][1] = r3;
            }
#pragma unroll
            for (int mf = 0; mf < 4; mf++)
#pragma unroll
                for (int nf = 0; nf < 8; nf++)
                    mma_f16(acc[mf][nf], a[mf], b[nf]);
        }
    }

    // epilogue: bias + scatter fp32
    const int g = lane >> 2, t2 = lane & 3;
#pragma unroll
    for (int mf = 0; mf < 4; mf++) {
#pragma unroll
        for (int nf = 0; nf < 8; nf++) {
            int row0 = wm + mf * 16 + g;
            int colL = wn + nf * 8 + t2 * 2;
            float b0 = sbias[colL], b1 = sbias[colL + 1];
            int lr = tm + row0;
            if (lr < ne) {
                int tok = stoks[row0];
                float2 o = make_float2(acc[mf][nf][0] + b0, acc[mf][nf][1] + b1);
                *reinterpret_cast<float2*>(&out[(size_t)tok * D_DIM + n0 + colL]) = o;
            }
            if (lr + 8 < ne) {
                int tok = stoks[row0 + 8];
                float2 o = make_float2(acc[mf][nf][2] + b0, acc[mf][nf][3] + b1);
                *reinterpret_cast<float2*>(&out[(size_t)tok * D_DIM + n0 + colL]) = o;
            }
        }
    }
}

// ---------------- launch ----------------
extern "C" void kernel_launch(void* const* d_in, const int* in_sizes, int n_in,
                              void* d_out, int out_size)
{
    const float* X    = (const float*)d_in[0];
    const int*   disp = (const int*)d_in[1];
    const float* W1   = (const float*)d_in[2];
    const float* B1   = (const float*)d_in[3];
    const float* W2   = (const float*)d_in[4];
    const float* B2   = (const float*)d_in[5];
    float*       out  = (float*)d_out;

    cudaFuncSetAttribute(gemm1_kernel, cudaFuncAttributeMaxDynamicSharedMemorySize, DSMEM_B);
    cudaFuncSetAttribute(gemm2_kernel, cudaFuncAttributeMaxDynamicSharedMemorySize, DSMEM_B);

    __half* w1h; cudaGetSymbolAddress((void**)&w1h, g_W1h);
    __half* w2h; cudaGetSymbolAddress((void**)&w2h, g_W2h);

    const int WELEMS = N_EXP * D_DIM * F_DIM;   // 67,108,864

    dispatch_kernel<<<1, 1024>>>(disp);
    gather_x_kernel<<<T_TOKENS / 2, 256>>>(X);
    convert_w_kernel<<<WELEMS / (256 * 8), 256>>>(W1, w1h);
    convert_w_kernel<<<WELEMS / (256 * 8), 256>>>(W2, w2h);
    gemm1_kernel<<<dim3(F_DIM / BN, 8, N_EXP), NTH, DSMEM_B>>>(B1);
    gemm2_kernel<<<dim3(D_DIM / BN, 8, N_EXP), NTH, DSMEM_B>>>(B2, out);
}

// round 12
// speedup vs baseline: 2.2731x; 1.0149x over previous
#include <cuda_runtime.h>
#include <cuda_fp16.h>
#include <cstdint>

#define T_TOKENS 32768
#define D_DIM    512
#define F_DIM    2048
#define N_EXP    64

#define BM 128
#define BN 128
#define BK 32
#define NTH 128

// smem geometry (bank-conflict-engineered strides)
#define A_ROW_B   80                      // 32 halves + pad -> banks 20r%32, LDSM conflict-free
#define B_ROW_B   272                     // 128 halves + pad -> banks 4k%32, LDSM.T conflict-free
#define A_STAGE_B (BM * A_ROW_B)          // 10240
#define B_STAGE_B (BK * B_ROW_B)          // 8704
#define STAGES    3
#define DSMEM_B   (STAGES * (A_STAGE_B + B_STAGE_B))   // 56832 -> 2 CTAs/SM

#define WELEMS    (N_EXP * D_DIM * F_DIM)              // 67,108,864

// ---------------- device scratch ----------------
__device__ int    g_offsets[N_EXP + 1];
__device__ int    g_tok[T_TOKENS];
__device__ __half g_Xg [(size_t)T_TOKENS * D_DIM];       // 32 MB  fp16 X, expert-gathered order
__device__ __half g_Hh [(size_t)T_TOKENS * F_DIM];       // 128 MB fp16 intermediate (compact)
__device__ __half g_W1h[(size_t)WELEMS];                 // 134 MB
__device__ __half g_W2h[(size_t)WELEMS];                 // 134 MB

// ---------------- helpers ----------------
__device__ __forceinline__ float gelu_exact(float x) {
    return 0.5f * x * (1.0f + erff(x * 0.70710678118654752f));
}

__device__ __forceinline__ uint32_t smem_u32(const void* p) {
    uint32_t a;
    asm("{ .reg .u64 t; cvta.to.shared.u64 t, %1; cvt.u32.u64 %0, t; }" : "=r"(a) : "l"(p));
    return a;
}

__device__ __forceinline__ void cp16(uint32_t dst, const void* src) {
    asm volatile("cp.async.cg.shared.global [%0], [%1], 16;" :: "r"(dst), "l"(src));
}
#define CP_COMMIT() asm volatile("cp.async.commit_group;")

#define LDSM_X4(r, addr) \
    asm volatile("ldmatrix.sync.aligned.m8n8.x4.shared.b16 {%0,%1,%2,%3}, [%4];" \
        : "=r"((r)[0]), "=r"((r)[1]), "=r"((r)[2]), "=r"((r)[3]) : "r"(addr))

#define LDSM_X4_T(r0, r1, r2, r3, addr) \
    asm volatile("ldmatrix.sync.aligned.m8n8.x4.trans.shared.b16 {%0,%1,%2,%3}, [%4];" \
        : "=r"(r0), "=r"(r1), "=r"(r2), "=r"(r3) : "r"(addr))

__device__ __forceinline__ void mma_f16(float* c, const uint32_t* a, const uint32_t* b) {
    asm volatile(
        "mma.sync.aligned.m16n8k16.row.col.f32.f16.f16.f32 "
        "{%0,%1,%2,%3}, {%4,%5,%6,%7}, {%8,%9}, {%0,%1,%2,%3};"
        : "+f"(c[0]), "+f"(c[1]), "+f"(c[2]), "+f"(c[3])
        : "r"(a[0]), "r"(a[1]), "r"(a[2]), "r"(a[3]), "r"(b[0]), "r"(b[1]));
}

__device__ __forceinline__ uint32_t pack_h2(float lo, float hi) {
    uint32_t d;
    asm("cvt.rn.f16x2.f32 %0, %1, %2;" : "=r"(d) : "f"(hi), "f"(lo));  // first src -> upper
    return d;
}

// ---------------- fused dispatch (one CTA) ----------------
__global__ void dispatch_kernel(const int* __restrict__ disp) {
    __shared__ int cnt[N_EXP];
    __shared__ int off[N_EXP];
    const int tid = threadIdx.x;                 // 1024 threads
    if (tid < N_EXP) cnt[tid] = 0;
    __syncthreads();
    for (int t = tid; t < T_TOKENS; t += 1024) atomicAdd(&cnt[disp[t]], 1);
    __syncthreads();
    if (tid == 0) {
        int s = 0;
        for (int e = 0; e < N_EXP; e++) { off[e] = s; g_offsets[e] = s; s += cnt[e]; }
        g_offsets[N_EXP] = s;
    }
    __syncthreads();
    if (tid < N_EXP) cnt[tid] = 0;               // reuse as cursors
    __syncthreads();
    for (int t = tid; t < T_TOKENS; t += 1024) {
        int e = disp[t];
        int p = atomicAdd(&cnt[e], 1);
        g_tok[off[e] + p] = t;
    }
}

// ---------------- gather + convert X: g_Xg[slot] = fp16(X[g_tok[slot]]) ----------------
__global__ void gather_x_kernel(const float* __restrict__ X) {
    const int slot  = blockIdx.x * 2 + (threadIdx.x >> 7);
    const int local = threadIdx.x & 127;
    const int tok   = g_tok[slot];
    float4 v = *reinterpret_cast<const float4*>(&X[(size_t)tok * D_DIM + local * 4]);
    uint2 o;
    o.x = pack_h2(v.x, v.y); o.y = pack_h2(v.z, v.w);
    *reinterpret_cast<uint2*>(&g_Xg[(size_t)slot * D_DIM + local * 4]) = o;
}

// ---------------- W fp32 -> fp16 (standalone, used for W1) ----------------
__global__ void convert_w_kernel(const float* __restrict__ W, __half* __restrict__ Wh) {
    size_t i = ((size_t)blockIdx.x * 256 + threadIdx.x) * 8;
    float4 v0 = *reinterpret_cast<const float4*>(&W[i]);
    float4 v1 = *reinterpret_cast<const float4*>(&W[i + 4]);
    uint4 o;
    o.x = pack_h2(v0.x, v0.y); o.y = pack_h2(v0.z, v0.w);
    o.z = pack_h2(v1.x, v1.y); o.w = pack_h2(v1.z, v1.w);
    *reinterpret_cast<uint4*>(&Wh[i]) = o;
}

// ================= GEMM kernels (fp16 HMMA, dual-operand 3-stage cp.async) =================
// 128 threads = 4 warps (2x2), warp tile 64x64, one __syncthreads per K-tile.

// ---- GEMM1: H = gelu(Xg @ W1h + b1) -> g_Hh (compact). Grid (16, 9, 64). ----
// blockIdx.y == 8: heterogeneous converter CTAs — convert W2 fp32->fp16 chunk,
// overlapping the (DRAM-idle) tensor-bound GEMM waves. 1024 CTAs x 65536 elems.
__global__ __launch_bounds__(NTH, 2) void gemm1_kernel(
    const float* __restrict__ W2, const float* __restrict__ B1)
{
    extern __shared__ char dsm[];
    __shared__ float sbias[BN];

    // ---- converter role ----
    if (blockIdx.y == 8) {
        const int cid = blockIdx.x + 16 * blockIdx.z;          // 0..1023
        const size_t base_i = (size_t)cid * (WELEMS / 1024);   // 65536 elems
        const int tid = threadIdx.x;
#pragma unroll 4
        for (int it = 0; it < 64; it++) {
            size_t i = base_i + (size_t)it * 1024 + tid * 8;
            float4 v0 = *reinterpret_cast<const float4*>(&W2[i]);
            float4 v1 = *reinterpret_cast<const float4*>(&W2[i + 4]);
            uint4 o;
            o.x = pack_h2(v0.x, v0.y); o.y = pack_h2(v0.z, v0.w);
            o.z = pack_h2(v1.x, v1.y); o.w = pack_h2(v1.z, v1.w);
            *reinterpret_cast<uint4*>(&g_W2h[i]) = o;
        }
        return;
    }

    // ---- GEMM role ----
    const int e    = blockIdx.z;
    const int base = g_offsets[e];
    const int ne   = g_offsets[e + 1] - base;
    const int tm   = blockIdx.y * BM;
    if (tm >= ne) return;
    const int n0   = blockIdx.x * BN;

    const int tid  = threadIdx.x;
    const int warp = tid >> 5, lane = tid & 31;
    const int wm   = (warp & 1) * 64;
    const int wn   = (warp >> 1) * 64;

    sbias[tid] = B1[e * F_DIM + n0 + tid];

    const uint32_t sb = smem_u32(dsm);
    uint32_t uA[STAGES], uB[STAGES];
#pragma unroll
    for (int s = 0; s < STAGES; s++) {
        uA[s] = sb + s * A_STAGE_B;
        uB[s] = sb + STAGES * A_STAGE_B + s * B_STAGE_B;
    }

    float acc[4][8][4];
#pragma unroll
    for (int mf = 0; mf < 4; mf++)
#pragma unroll
        for (int nf = 0; nf < 8; nf++)
#pragma unroll
            for (int c = 0; c < 4; c++) acc[mf][nf][c] = 0.f;

    const int KIT = D_DIM / BK;  // 16

    auto load_stage = [&](int kt) {
        const int k0 = kt * BK;
        const int s  = kt % STAGES;
#pragma unroll
        for (int i = 0; i < 4; i++) {                        // A: 128 rows x 4 segs
            int idx = tid + i * NTH;
            int r = idx >> 2, cc = idx & 3;
            int arow = base + tm + r; if (arow > T_TOKENS - 1) arow = T_TOKENS - 1;
            cp16(uA[s] + r * A_ROW_B + cc * 16, &g_Xg[(size_t)arow * D_DIM + k0 + cc * 8]);
        }
#pragma unroll
        for (int i = 0; i < 4; i++) {                        // B: 32 k-rows x 16 segs
            int idx = tid + i * NTH;
            int kr = idx >> 4, seg = idx & 15;
            cp16(uB[s] + kr * B_ROW_B + seg * 16,
                 &g_W1h[((size_t)e * D_DIM + k0 + kr) * F_DIM + n0 + seg * 8]);
        }
        CP_COMMIT();
    };

    load_stage(0);
    load_stage(1);

    for (int kt = 0; kt < KIT; kt++) {
        if (kt + 1 < KIT) { asm volatile("cp.async.wait_group 1;"); }
        else              { asm volatile("cp.async.wait_group 0;"); }
        __syncthreads();
        if (kt + 2 < KIT) load_stage(kt + 2);
        const uint32_t ua = uA[kt % STAGES];
        const uint32_t ub = uB[kt % STAGES];
#pragma unroll
        for (int c = 0; c < 2; c++) {
            uint32_t a[4][4];
#pragma unroll
            for (int mf = 0; mf < 4; mf++) {
                int row = wm + mf * 16 + (lane & 7) + ((lane >> 3) & 1) * 8;
                LDSM_X4(a[mf], ua + row * A_ROW_B + ((lane >> 4) + 2 * c) * 16);
            }
            uint32_t b[8][2];
#pragma unroll
            for (int p = 0; p < 4; p++) {
                int k = c * 16 + ((lane >> 3) & 1) * 8 + (lane & 7);
                int n = wn + p * 16 + (lane >> 4) * 8;
                uint32_t r0, r1, r2, r3;
                LDSM_X4_T(r0, r1, r2, r3, ub + k * B_ROW_B + n * 2);
                b[2 * p][0] = r0; b[2 * p][1] = r1;
                b[2 * p + 1][0] = r2; b[2 * p + 1][1] = r3;
            }
#pragma unroll
            for (int mf = 0; mf < 4; mf++)
#pragma unroll
                for (int nf = 0; nf < 8; nf++)
                    mma_f16(acc[mf][nf], a[mf], b[nf]);
        }
    }

    // epilogue: bias + exact gelu -> fp16 g_Hh (compact rows)
    const int g = lane >> 2, t2 = lane & 3;
#pragma unroll
    for (int mf = 0; mf < 4; mf++) {
#pragma unroll
        for (int nf = 0; nf < 8; nf++) {
            int row0 = wm + mf * 16 + g;
            int colL = wn + nf * 8 + t2 * 2;
            float b0 = sbias[colL], b1 = sbias[colL + 1];
            int lr = tm + row0;
            if (lr < ne) {
                uint32_t h = pack_h2(gelu_exact(acc[mf][nf][0] + b0),
                                     gelu_exact(acc[mf][nf][1] + b1));
                *reinterpret_cast<uint32_t*>(&g_Hh[(size_t)(base + lr) * F_DIM + n0 + colL]) = h;
            }
            if (lr + 8 < ne) {
                uint32_t h = pack_h2(gelu_exact(acc[mf][nf][2] + b0),
                                     gelu_exact(acc[mf][nf][3] + b1));
                *reinterpret_cast<uint32_t*>(&g_Hh[(size_t)(base + lr + 8) * F_DIM + n0 + colL]) = h;
            }
        }
    }
}

// ---- GEMM2: out = Hh @ W2h + b2, scattered fp32. Grid (4, 8, 64). ----
__global__ __launch_bounds__(NTH, 2) void gemm2_kernel(const float* __restrict__ B2,
                                                       float* __restrict__ out)
{
    extern __shared__ char dsm[];
    __shared__ int   stoks[BM];
    __shared__ float sbias[BN];

    const int e    = blockIdx.z;
    const int base = g_offsets[e];
    const int ne   = g_offsets[e + 1] - base;
    const int tm   = blockIdx.y * BM;
    if (tm >= ne) return;
    const int n0   = blockIdx.x * BN;

    const int tid  = threadIdx.x;
    const int warp = tid >> 5, lane = tid & 31;
    const int wm   = (warp & 1) * 64;
    const int wn   = (warp >> 1) * 64;

    stoks[tid] = (tm + tid < ne) ? g_tok[base + tm + tid] : -1;
    sbias[tid] = B2[e * D_DIM + n0 + tid];

    const uint32_t sb = smem_u32(dsm);
    uint32_t uA[STAGES], uB[STAGES];
#pragma unroll
    for (int s = 0; s < STAGES; s++) {
        uA[s] = sb + s * A_STAGE_B;
        uB[s] = sb + STAGES * A_STAGE_B + s * B_STAGE_B;
    }

    float acc[4][8][4];
#pragma unroll
    for (int mf = 0; mf < 4; mf++)
#pragma unroll
        for (int nf = 0; nf < 8; nf++)
#pragma unroll
            for (int c = 0; c < 4; c++) acc[mf][nf][c] = 0.f;

    const int KIT = F_DIM / BK;  // 64

    auto load_stage = [&](int kt) {
        const int k0 = kt * BK;
        const int s  = kt % STAGES;
#pragma unroll
        for (int i = 0; i < 4; i++) {
            int idx = tid + i * NTH;
            int r = idx >> 2, cc = idx & 3;
            int arow = base + tm + r; if (arow > T_TOKENS - 1) arow = T_TOKENS - 1;
            cp16(uA[s] + r * A_ROW_B + cc * 16, &g_Hh[(size_t)arow * F_DIM + k0 + cc * 8]);
        }
#pragma unroll
        for (int i = 0; i < 4; i++) {
            int idx = tid + i * NTH;
            int kr = idx >> 4, seg = idx & 15;
            cp16(uB[s] + kr * B_ROW_B + seg * 16,
                 &g_W2h[((size_t)e * F_DIM + k0 + kr) * D_DIM + n0 + seg * 8]);
        }
        CP_COMMIT();
    };

    load_stage(0);
    load_stage(1);

    for (int kt = 0; kt < KIT; kt++) {
        if (kt + 1 < KIT) { asm volatile("cp.async.wait_group 1;"); }
        else              { asm volatile("cp.async.wait_group 0;"); }
        __syncthreads();
        if (kt + 2 < KIT) load_stage(kt + 2);
        const uint32_t ua = uA[kt % STAGES];
        const uint32_t ub = uB[kt % STAGES];
#pragma unroll
        for (int c = 0; c < 2; c++) {
            uint32_t a[4][4];
#pragma unroll
            for (int mf = 0; mf < 4; mf++) {
                int row = wm + mf * 16 + (lane & 7) + ((lane >> 3) & 1) * 8;
                LDSM_X4(a[mf], ua + row * A_ROW_B + ((lane >> 4) + 2 * c) * 16);
            }
            uint32_t b[8][2];
#pragma unroll
            for (int p = 0; p < 4; p++) {
                int k = c * 16 + ((lane >> 3) & 1) * 8 + (lane & 7);
                int n = wn + p * 16 + (lane >> 4) * 8;
                uint32_t r0, r1, r2, r3;
                LDSM_X4_T(r0, r1, r2, r3, ub + k * B_ROW_B + n * 2);
                b[2 * p][0] = r0; b[2 * p][1] = r1;
                b[2 * p + 1][0] = r2; b[2 * p + 1][1] = r3;
            }
#pragma unroll
            for (int mf = 0; mf < 4; mf++)
#pragma unroll
                for (int nf = 0; nf < 8; nf++)
                    mma_f16(acc[mf][nf], a[mf], b[nf]);
        }
    }

    // epilogue: bias + scatter fp32
    const int g = lane >> 2, t2 = lane & 3;
#pragma unroll
    for (int mf = 0; mf < 4; mf++) {
#pragma unroll
        for (int nf = 0; nf < 8; nf++) {
            int row0 = wm + mf * 16 + g;
            int colL = wn + nf * 8 + t2 * 2;
            float b0 = sbias[colL], b1 = sbias[colL + 1];
            int lr = tm + row0;
            if (lr < ne) {
                int tok = stoks[row0];
                float2 o = make_float2(acc[mf][nf][0] + b0, acc[mf][nf][1] + b1);
                *reinterpret_cast<float2*>(&out[(size_t)tok * D_DIM + n0 + colL]) = o;
            }
            if (lr + 8 < ne) {
                int tok = stoks[row0 + 8];
                float2 o = make_float2(acc[mf][nf][2] + b0, acc[mf][nf][3] + b1);
                *reinterpret_cast<float2*>(&out[(size_t)tok * D_DIM + n0 + colL]) = o;
            }
        }
    }
}

// ---------------- launch ----------------
extern "C" void kernel_launch(void* const* d_in, const int* in_sizes, int n_in,
                              void* d_out, int out_size)
{
    const float* X    = (const float*)d_in[0];
    const int*   disp = (const int*)d_in[1];
    const float* W1   = (const float*)d_in[2];
    const float* B1   = (const float*)d_in[3];
    const float* W2   = (const float*)d_in[4];
    const float* B2   = (const float*)d_in[5];
    float*       out  = (float*)d_out;

    cudaFuncSetAttribute(gemm1_kernel, cudaFuncAttributeMaxDynamicSharedMemorySize, DSMEM_B);
    cudaFuncSetAttribute(gemm2_kernel, cudaFuncAttributeMaxDynamicSharedMemorySize, DSMEM_B);

    __half* w1h; cudaGetSymbolAddress((void**)&w1h, g_W1h);

    dispatch_kernel<<<1, 1024>>>(disp);
    gather_x_kernel<<<T_TOKENS / 2, 256>>>(X);
    convert_w_kernel<<<WELEMS / (256 * 8), 256>>>(W1, w1h);
    // gemm1 also converts W2 -> g_W2h via its blockIdx.y==8 converter CTAs
    gemm1_kernel<<<dim3(F_DIM / BN, 9, N_EXP), NTH, DSMEM_B>>>(W2, B1);
    gemm2_kernel<<<dim3(D_DIM / BN, 8, N_EXP), NTH, DSMEM_B>>>(B2, out);
}